// round 10
// baseline (speedup 1.0000x reference)
#include <cuda_runtime.h>
#include <math.h>

// ProCoUNLoss — single fused kernel. Per-element f32 ops mirror the reference;
// the class-norm is an exact f64 tree (bit-identical to prior passing rounds);
// x and L are bit-exact; lnu is computed to ~1e-6 (budget ~3e-6), and the
// reference's Miller-recurrence contamination is replicated analytically.

namespace {
constexpr int NB = 256;
constexpr int DD = 128;
constexpr int CC = 1000;
constexpr int TN = 16;   // n tile (2 outputs/thread)
constexpr int TC = 32;   // c tile
}

// ---------- packed f32x2 helpers ----------
__device__ __forceinline__ unsigned long long add2(unsigned long long a,
                                                   unsigned long long b) {
    unsigned long long r;
    asm("add.rn.f32x2 %0, %1, %2;" : "=l"(r) : "l"(a), "l"(b));
    return r;
}
__device__ __forceinline__ unsigned long long mul2(unsigned long long a,
                                                   unsigned long long b) {
    unsigned long long r;
    asm("mul.rn.f32x2 %0, %1, %2;" : "=l"(r) : "l"(a), "l"(b));
    return r;
}
__device__ __forceinline__ unsigned long long fma2(unsigned long long a,
                                                   unsigned long long b,
                                                   unsigned long long c) {
    unsigned long long r;
    asm("fma.rn.f32x2 %0, %1, %2, %3;" : "=l"(r) : "l"(a), "l"(b), "l"(c));
    return r;
}
__device__ __forceinline__ float hadd2(unsigned long long v) {
    unsigned int lo, hi;
    asm("mov.b64 {%0, %1}, %2;" : "=r"(lo), "=r"(hi) : "l"(v));
    return __fadd_rn(__uint_as_float(lo), __uint_as_float(hi));
}

// ---------- double-single log (only for L, which needs bit-exactness) ----
__device__ __forceinline__ float2 ds_log_core(float mh, float ef) {
    float ah = __fadd_rn(mh, -1.0f);               // exact (Sterbenz)
    float bh = __fadd_rn(mh, 1.0f);
    float tb = __fsub_rn(bh, 1.0f);                // TwoSum residual for m+1
    float bl = __fadd_rn(__fsub_rn(1.0f, __fsub_rn(bh, tb)), __fsub_rn(mh, tb));
    float uh = __fdiv_rn(ah, bh);                  // u = (m-1)/(m+1), DS
    float rr = __fmaf_rn(-uh, bh, ah);
    rr = __fadd_rn(rr, -__fmul_rn(uh, bl));
    float ul = __fdiv_rn(rr, bh);
    float u2 = __fmul_rn(uh, uh);                  // atanh series to u^9
    float p  = u2 * __fmaf_rn(u2, __fmaf_rn(u2, __fmaf_rn(u2, 0.11111111f,
                    0.14285715f), 0.2f), 0.33333334f);
    float lnmh = __fmul_rn(2.0f, uh);              // exact
    float lnml = __fmaf_rn(lnmh, p, __fmul_rn(2.0f, ul));
    const float LN2H = 0.6931471824645996f;
    const float LN2L = -1.9046542e-9f;
    float eh = __fmul_rn(ef, LN2H);
    float el = __fmaf_rn(ef, LN2H, -eh);
    el = __fmaf_rn(ef, LN2L, el);
    float sh = __fadd_rn(eh, lnmh);                // TwoSum(eh, lnmh)
    float ts = __fsub_rn(sh, eh);
    float sl = __fadd_rn(__fsub_rn(eh, __fsub_rn(sh, ts)), __fsub_rn(lnmh, ts));
    return make_float2(sh, __fadd_rn(sl, __fadd_rn(el, lnml)));
}

__device__ __forceinline__ float ds_log_f32(float x) {  // fl32(log(x)), ~exact
    int ix = __float_as_int(x);
    int e  = ((ix >> 23) & 255) - 127;
    float m = __int_as_float((ix & 0x007fffff) | 0x3f800000);
    if (m > 1.4142135f) { m *= 0.5f; e += 1; }
    float2 r = ds_log_core(m, (float)e);
    return __fadd_rn(r.x, r.y);
}

// log1p(v), v in (0.02, 0.9]: 2*atanh(u), u=v/(2+v), series to u^11 (~1.5e-7)
__device__ __forceinline__ float log1p_v(float v) {
    float u  = __fdiv_rn(v, __fadd_rn(2.0f, v));
    float u2 = __fmul_rn(u, u);
    float p  = __fmaf_rn(u2, __fmaf_rn(u2, __fmaf_rn(u2, __fmaf_rn(u2,
                 0.09090909f, 0.11111111f), 0.14285715f), 0.2f), 0.33333334f);
    return __fmul_rn(__fadd_rn(u, u), __fmaf_rn(u2, p, 1.0f));
}

// log1p(z), z in [0, 0.19]: series to z^7 (abs err < 2e-7)
__device__ __forceinline__ float log1p_small(float z) {
    float r = __fmaf_rn(z, 0.14285715f, -0.16666667f);
    r = __fmaf_rn(z, r, 0.2f);
    r = __fmaf_rn(z, r, -0.25f);
    r = __fmaf_rn(z, r, 0.33333334f);
    r = __fmaf_rn(z, r, -0.5f);
    r = __fmaf_rn(z, r, 1.0f);
    return __fmul_rn(z, r);
}

// p(t) = u1(t)/63 + u2(t)/63^2 + u3(t)/63^3  (Debye u-polynomials)
__device__ __forceinline__ float pser_f(float t) {
    float t2 = t * t;
    float a = t * (3.0f - 5.0f * t2) * (1.0f / 1512.0f);
    float b = t2 * (81.0f + t2 * (-462.0f + 385.0f * t2)) * 2.1870954e-7f;
    float c = t2 * t * (30375.0f + t2 * (-369603.0f + t2 * (765765.0f - 425425.0f * t2)))
              * 9.643249e-12f;
    return a + b + c;
}

// Miller-recurrence contamination of the reference (start M=126):
// log1p(-rho63) - log1p(rho0). lp63 = log1p((63+dw63)/x) from caller.
__device__ __forceinline__ float miller_corr(float x, float w63, float lp63) {
    float w127  = __fsqrt_rn(__fmaf_rn(x, x, 16129.0f));
    float dw127 = __fdividef(16129.0f, __fadd_rn(w127, x));
    float L127  = __logf(__fadd_rn(1.0f,
                     __fdividef(__fadd_rn(127.0f, dw127), x)));
    float g63 = __fmaf_rn(-254.0f, L127, __fmaf_rn(126.0f, lp63,
                  2.0f * __fdividef(12160.0f, __fadd_rn(w127, w63))));
    float g0  = __fmaf_rn(-254.0f, L127, __fadd_rn(dw127, dw127));
    float r63 = __expf(g63);   // underflow to 0 at small x: correct
    float r0  = __expf(g0);
    return -(r63 + r0) - 0.5f * (r63 * r63 - r0 * r0);
}

// Per-element epilogue: exact-sum -> x -> lnu -> reference association.
__device__ __forceinline__ float epilogue(float s, float kc, float lc) {
    // x = f32(sqrt(s+kc)) via Newton-refined sqrt (bit-matches f64 path)
    float r0  = __fsqrt_rn(s);
    float e1  = __fmaf_rn(r0, r0, -s);
    float num = __fsub_rn(e1, kc);
    float x   = __fsub_rn(r0, __fdiv_rn(num, __fadd_rn(r0, r0)));

    float w   = __fsqrt_rn(__fmaf_rn(x, x, 3969.0f));
    float dwx = __fdiv_rn(3969.0f, __fadd_rn(w, x));   // w - x, stable
    float v   = __fdiv_rn(__fadd_rn(63.0f, dwx), x);

    float lp  = log1p_v(v);                            // log1p(v), ~1.5e-7
    float L   = ds_log_f32(x);                         // bit-exact f32 log

    float hlw = 0.5f * __fadd_rn(L, log1p_small(__fdividef(dwx, x)));
    float pp  = pser_f(__fdividef(63.0f, w));
    float lnS = __fmaf_rn(-0.5f * pp, pp, pp);         // log1p(pp)
    float corr = miller_corr(x, w, lp);

    // lnu = dwx - 63*lp - hlw - 0.5*log(2pi) + lnS + corr  (budget ~3e-6)
    float lnu = __fmaf_rn(-63.0f, lp, dwx);
    lnu = __fsub_rn(lnu, hlw);
    lnu = __fadd_rn(lnu, -0.91893853f);
    lnu = __fadd_rn(lnu, lnS);
    lnu = __fadd_rn(lnu, corr);

    // Reference's f32 association: ((lnu + x) - 63*L) - logc
    return __fsub_rn(__fsub_rn(__fadd_rn(lnu, x), __fmul_rn(63.0f, L)), lc);
}

// Fused kernel: per-block proto build (exact f64 norm + Markstein div),
// then 16n x 32c reduce, 2 outputs/thread.
__global__ __launch_bounds__(256, 4)
void proco_kernel(const float* __restrict__ feat,
                  const float* __restrict__ Ave,
                  const float* __restrict__ kappa,
                  const float* __restrict__ logc,
                  float* __restrict__ out) {
    __shared__ float fs[TN][DD + 4];
    __shared__ float ps[TC][DD + 4];

    const int c0  = blockIdx.x * TC;
    const int n0  = blockIdx.y * TN;
    const int tid = threadIdx.x;

    for (int i = tid; i < TN * DD / 4; i += 256) {
        int r = i >> 5, q = i & 31;
        *reinterpret_cast<float4*>(&fs[r][4 * q]) =
            reinterpret_cast<const float4*>(feat)[(n0 + r) * (DD / 4) + q];
    }
    for (int i = tid; i < TC * DD / 4; i += 256) {
        int r = i >> 5, q = i & 31;
        int c = c0 + r;
        float4 val = (c < CC)
            ? reinterpret_cast<const float4*>(Ave)[c * (DD / 4) + q]
            : make_float4(0.f, 0.f, 0.f, 0.f);
        *reinterpret_cast<float4*>(&ps[r][4 * q]) = val;
    }
    __syncthreads();

    // Proto in place: warp w owns tile rows 4w..4w+3.
    {
        const int wrp = tid >> 5, lane = tid & 31;
        #pragma unroll
        for (int j = 0; j < 4; ++j) {
            const int cr = 4 * wrp + j;
            float a0 = ps[cr][lane];
            float a1 = ps[cr][lane + 32];
            float a2 = ps[cr][lane + 64];
            float a3 = ps[cr][lane + 96];
            // exact f64 norm, bit-identical order to prior passing rounds
            double sd = (double)__fmul_rn(a0, a0);
            sd += (double)__fmul_rn(a1, a1);
            sd += (double)__fmul_rn(a2, a2);
            sd += (double)__fmul_rn(a3, a3);
            #pragma unroll
            for (int off = 16; off; off >>= 1)
                sd += __shfl_xor_sync(0xffffffffu, sd, off);
            float nrm = fmaxf((float)sqrt(sd), 1e-12f);
            const int c = c0 + cr;
            float kap = (c < CC) ? kappa[c] : 0.0f;
            float rh  = __frcp_rn(nrm);
            // Markstein correctly-rounded division a/nrm, then * kappa
            #define MDIV(a, dst) { float q0 = __fmul_rn((a), rh);               \
                float e = __fmaf_rn(-nrm, q0, (a));                             \
                float q = __fmaf_rn(e, rh, q0);                                 \
                dst = __fmul_rn(kap, q); }
            MDIV(a0, ps[cr][lane])
            MDIV(a1, ps[cr][lane + 32])
            MDIV(a2, ps[cr][lane + 64])
            MDIV(a3, ps[cr][lane + 96])
            #undef MDIV
        }
    }
    __syncthreads();

    const int cl = tid & 31;   // class lane (coalesced stores)
    const int ng = tid >> 5;   // thread owns n rows ng and ng+8

    float s0 = 0.f, k0 = 0.f;  // Kahan pairs, one per output
    float s1 = 0.f, k1 = 0.f;

    #pragma unroll
    for (int grp = 0; grp < 16; ++grp) {
        const int d0 = grp * 8;
        const ulonglong2 pa = *reinterpret_cast<const ulonglong2*>(&ps[cl][d0]);
        const ulonglong2 pb = *reinterpret_cast<const ulonglong2*>(&ps[cl][d0 + 4]);
        #define GROUP(row, S, K) {                                              \
            const ulonglong2 fa = *reinterpret_cast<const ulonglong2*>(&fs[row][d0]);     \
            const ulonglong2 fb = *reinterpret_cast<const ulonglong2*>(&fs[row][d0 + 4]); \
            unsigned long long t0 = add2(pa.x, fa.x);                           \
            unsigned long long t1 = add2(pa.y, fa.y);                           \
            unsigned long long t2 = add2(pb.x, fb.x);                           \
            unsigned long long t3 = add2(pb.y, fb.y);                           \
            unsigned long long g2 = mul2(t0, t0);                               \
            g2 = fma2(t1, t1, g2);                                              \
            g2 = fma2(t2, t2, g2);                                              \
            g2 = fma2(t3, t3, g2);                                              \
            float g  = hadd2(g2);                                               \
            float y  = __fsub_rn(g, K);                                         \
            float sn = __fadd_rn(S, y);                                         \
            K = __fsub_rn(__fsub_rn(sn, S), y);                                 \
            S = sn; }
        GROUP(ng,     s0, k0)
        GROUP(ng + 8, s1, k1)
        #undef GROUP
    }

    const int c = c0 + cl;
    if (c >= CC) return;
    const float lc = logc[c];
    out[(n0 + ng)     * CC + c] = epilogue(s0, k0, lc);
    out[(n0 + ng + 8) * CC + c] = epilogue(s1, k1, lc);
}

extern "C" void kernel_launch(void* const* d_in, const int* in_sizes, int n_in,
                              void* d_out, int out_size) {
    const float* feat  = (const float*)d_in[0];
    // d_in[1]: labels (int64) — unused by the deterministic forward math.
    const float* Ave   = (const float*)d_in[2];
    const float* kappa = (const float*)d_in[3];
    const float* logc  = (const float*)d_in[4];
    float* out = (float*)d_out;

    proco_kernel<<<dim3(CC / TC + (CC % TC != 0), NB / TN), 256>>>(
        feat, Ave, kappa, logc, out);
}

// round 11
// speedup vs baseline: 1.9570x; 1.9570x over previous
#include <cuda_runtime.h>
#include <math.h>

// ProCoUNLoss — two-kernel structure (norms computed once per class) with the
// slim f32 epilogue. Per-element f32 ops mirror the reference; reductions are
// exact; x and L bit-exact; lnu to ~1e-6 incl. the reference's Miller-
// recurrence contamination.

namespace {
constexpr int NB   = 256;
constexpr int DD   = 128;
constexpr int CC   = 1000;
constexpr int CPAD = 1024;
constexpr int TN   = 8;    // n tile (1 output/thread)
constexpr int TC   = 32;   // c tile
}

__device__ float g_proto[CPAD * DD];  // fl(kappa * Ave_norm), zero padded

// ---------- packed f32x2 helpers ----------
__device__ __forceinline__ unsigned long long add2(unsigned long long a,
                                                   unsigned long long b) {
    unsigned long long r;
    asm("add.rn.f32x2 %0, %1, %2;" : "=l"(r) : "l"(a), "l"(b));
    return r;
}
__device__ __forceinline__ unsigned long long mul2(unsigned long long a,
                                                   unsigned long long b) {
    unsigned long long r;
    asm("mul.rn.f32x2 %0, %1, %2;" : "=l"(r) : "l"(a), "l"(b));
    return r;
}
__device__ __forceinline__ unsigned long long fma2(unsigned long long a,
                                                   unsigned long long b,
                                                   unsigned long long c) {
    unsigned long long r;
    asm("fma.rn.f32x2 %0, %1, %2, %3;" : "=l"(r) : "l"(a), "l"(b), "l"(c));
    return r;
}
__device__ __forceinline__ float hadd2(unsigned long long v) {
    unsigned int lo, hi;
    asm("mov.b64 {%0, %1}, %2;" : "=r"(lo), "=r"(hi) : "l"(v));
    return __fadd_rn(__uint_as_float(lo), __uint_as_float(hi));
}

// ---------- double-single log (only for L, which needs bit-exactness) ----
__device__ __forceinline__ float2 ds_log_core(float mh, float ef) {
    float ah = __fadd_rn(mh, -1.0f);               // exact (Sterbenz)
    float bh = __fadd_rn(mh, 1.0f);
    float tb = __fsub_rn(bh, 1.0f);                // TwoSum residual for m+1
    float bl = __fadd_rn(__fsub_rn(1.0f, __fsub_rn(bh, tb)), __fsub_rn(mh, tb));
    float uh = __fdiv_rn(ah, bh);                  // u = (m-1)/(m+1), DS
    float rr = __fmaf_rn(-uh, bh, ah);
    rr = __fadd_rn(rr, -__fmul_rn(uh, bl));
    float ul = __fdiv_rn(rr, bh);
    float u2 = __fmul_rn(uh, uh);                  // atanh series to u^9
    float p  = u2 * __fmaf_rn(u2, __fmaf_rn(u2, __fmaf_rn(u2, 0.11111111f,
                    0.14285715f), 0.2f), 0.33333334f);
    float lnmh = __fmul_rn(2.0f, uh);              // exact
    float lnml = __fmaf_rn(lnmh, p, __fmul_rn(2.0f, ul));
    const float LN2H = 0.6931471824645996f;
    const float LN2L = -1.9046542e-9f;
    float eh = __fmul_rn(ef, LN2H);
    float el = __fmaf_rn(ef, LN2H, -eh);
    el = __fmaf_rn(ef, LN2L, el);
    float sh = __fadd_rn(eh, lnmh);                // TwoSum(eh, lnmh)
    float ts = __fsub_rn(sh, eh);
    float sl = __fadd_rn(__fsub_rn(eh, __fsub_rn(sh, ts)), __fsub_rn(lnmh, ts));
    return make_float2(sh, __fadd_rn(sl, __fadd_rn(el, lnml)));
}

__device__ __forceinline__ float ds_log_f32(float x) {  // fl32(log(x)), ~exact
    int ix = __float_as_int(x);
    int e  = ((ix >> 23) & 255) - 127;
    float m = __int_as_float((ix & 0x007fffff) | 0x3f800000);
    if (m > 1.4142135f) { m *= 0.5f; e += 1; }
    float2 r = ds_log_core(m, (float)e);
    return __fadd_rn(r.x, r.y);
}

// log1p(v), v in (0.02, 0.9]: 2*atanh(u), u=v/(2+v), series to u^11 (~1.5e-7)
__device__ __forceinline__ float log1p_v(float v) {
    float u  = __fdiv_rn(v, __fadd_rn(2.0f, v));
    float u2 = __fmul_rn(u, u);
    float p  = __fmaf_rn(u2, __fmaf_rn(u2, __fmaf_rn(u2, __fmaf_rn(u2,
                 0.09090909f, 0.11111111f), 0.14285715f), 0.2f), 0.33333334f);
    return __fmul_rn(__fadd_rn(u, u), __fmaf_rn(u2, p, 1.0f));
}

// log1p(z), z in [0, 0.19]: series to z^7 (abs err < 2e-7)
__device__ __forceinline__ float log1p_small(float z) {
    float r = __fmaf_rn(z, 0.14285715f, -0.16666667f);
    r = __fmaf_rn(z, r, 0.2f);
    r = __fmaf_rn(z, r, -0.25f);
    r = __fmaf_rn(z, r, 0.33333334f);
    r = __fmaf_rn(z, r, -0.5f);
    r = __fmaf_rn(z, r, 1.0f);
    return __fmul_rn(z, r);
}

// p(t) = u1(t)/63 + u2(t)/63^2 + u3(t)/63^3  (Debye u-polynomials)
__device__ __forceinline__ float pser_f(float t) {
    float t2 = t * t;
    float a = t * (3.0f - 5.0f * t2) * (1.0f / 1512.0f);
    float b = t2 * (81.0f + t2 * (-462.0f + 385.0f * t2)) * 2.1870954e-7f;
    float c = t2 * t * (30375.0f + t2 * (-369603.0f + t2 * (765765.0f - 425425.0f * t2)))
              * 9.643249e-12f;
    return a + b + c;
}

// Miller-recurrence contamination of the reference (start M=126):
// log1p(-rho63) - log1p(rho0). lp63 = log1p((63+dw63)/x) from caller.
__device__ __forceinline__ float miller_corr(float x, float w63, float lp63) {
    float w127  = __fsqrt_rn(__fmaf_rn(x, x, 16129.0f));
    float dw127 = __fdividef(16129.0f, __fadd_rn(w127, x));
    float L127  = __logf(__fadd_rn(1.0f,
                     __fdividef(__fadd_rn(127.0f, dw127), x)));
    float g63 = __fmaf_rn(-254.0f, L127, __fmaf_rn(126.0f, lp63,
                  2.0f * __fdividef(12160.0f, __fadd_rn(w127, w63))));
    float g0  = __fmaf_rn(-254.0f, L127, __fadd_rn(dw127, dw127));
    float r63 = __expf(g63);   // underflow to 0 at small x: correct
    float r0  = __expf(g0);
    return -(r63 + r0) - 0.5f * (r63 * r63 - r0 * r0);
}

// Per-element epilogue: exact-sum -> x -> lnu -> reference association.
__device__ __forceinline__ float epilogue(float s, float kc, float lc) {
    // x = f32(sqrt(s+kc)) via Newton-refined sqrt (bit-matches f64 path)
    float r0  = __fsqrt_rn(s);
    float e1  = __fmaf_rn(r0, r0, -s);
    float num = __fsub_rn(e1, kc);
    float x   = __fsub_rn(r0, __fdiv_rn(num, __fadd_rn(r0, r0)));

    float w   = __fsqrt_rn(__fmaf_rn(x, x, 3969.0f));
    float dwx = __fdiv_rn(3969.0f, __fadd_rn(w, x));   // w - x, stable
    float v   = __fdiv_rn(__fadd_rn(63.0f, dwx), x);

    float lp  = log1p_v(v);                            // log1p(v), ~1.5e-7
    float L   = ds_log_f32(x);                         // bit-exact f32 log

    float hlw = 0.5f * __fadd_rn(L, log1p_small(__fdividef(dwx, x)));
    float pp  = pser_f(__fdividef(63.0f, w));
    float lnS = __fmaf_rn(-0.5f * pp, pp, pp);         // log1p(pp)
    float corr = miller_corr(x, w, lp);

    // lnu = dwx - 63*lp - hlw - 0.5*log(2pi) + lnS + corr  (budget ~3e-6)
    float lnu = __fmaf_rn(-63.0f, lp, dwx);
    lnu = __fsub_rn(lnu, hlw);
    lnu = __fadd_rn(lnu, -0.91893853f);
    lnu = __fadd_rn(lnu, lnS);
    lnu = __fadd_rn(lnu, corr);

    // Reference's f32 association: ((lnu + x) - 63*L) - logc
    return __fsub_rn(__fsub_rn(__fadd_rn(lnu, x), __fmul_rn(63.0f, L)), lc);
}

// Warp per class (norm computed ONCE per class): exact f64 tree norm, then
// proto = fl(kappa * div(Ave, nrm)) with Markstein correctly-rounded division.
__global__ void setup_kernel(const float* __restrict__ Ave,
                             const float* __restrict__ kappa) {
    const int w    = threadIdx.x >> 5;
    const int lane = threadIdx.x & 31;
    const int c    = blockIdx.x * 8 + w;
    if (c >= CPAD) return;

    if (c < CC) {
        float r0 = Ave[c * DD + lane];
        float r1 = Ave[c * DD + lane + 32];
        float r2 = Ave[c * DD + lane + 64];
        float r3 = Ave[c * DD + lane + 96];
        double s = (double)__fmul_rn(r0, r0);
        s += (double)__fmul_rn(r1, r1);
        s += (double)__fmul_rn(r2, r2);
        s += (double)__fmul_rn(r3, r3);
        #pragma unroll
        for (int off = 16; off; off >>= 1)
            s += __shfl_xor_sync(0xffffffffu, s, off);
        float nrm = fmaxf((float)sqrt(s), 1e-12f);
        float kap = kappa[c];
        float rh  = __frcp_rn(nrm);
        #define MDIV(a, dst) { float q0 = __fmul_rn((a), rh);                   \
            float e = __fmaf_rn(-nrm, q0, (a));                                 \
            float q = __fmaf_rn(e, rh, q0);                                     \
            dst = __fmul_rn(kap, q); }
        MDIV(r0, g_proto[c * DD + lane])
        MDIV(r1, g_proto[c * DD + lane + 32])
        MDIV(r2, g_proto[c * DD + lane + 64])
        MDIV(r3, g_proto[c * DD + lane + 96])
        #undef MDIV
    } else {
        #pragma unroll
        for (int j = 0; j < 4; ++j)
            g_proto[c * DD + lane + 32 * j] = 0.0f;
    }
}

// 8n x 32c tile, 256 threads, 1 output/thread. Exact sum of fl32(p+f)^2
// via packed-f32x2 groups-of-8 + scalar Kahan across 16 groups.
__global__ __launch_bounds__(256, 5)
void proco_kernel(const float* __restrict__ feat,
                  const float* __restrict__ logc,
                  float* __restrict__ out) {
    __shared__ float fs[TN][DD + 4];
    __shared__ float ps[TC][DD + 4];

    const int c0  = blockIdx.x * TC;
    const int n0  = blockIdx.y * TN;
    const int tid = threadIdx.x;

    for (int i = tid; i < TN * DD / 4; i += 256) {
        int r = i >> 5, q = i & 31;
        *reinterpret_cast<float4*>(&fs[r][4 * q]) =
            reinterpret_cast<const float4*>(feat)[(n0 + r) * (DD / 4) + q];
    }
    for (int i = tid; i < TC * DD / 4; i += 256) {
        int r = i >> 5, q = i & 31;
        *reinterpret_cast<float4*>(&ps[r][4 * q]) =
            reinterpret_cast<const float4*>(g_proto)[(c0 + r) * (DD / 4) + q];
    }
    __syncthreads();

    const int cl = tid & 31;   // class lane (coalesced stores)
    const int ng = tid >> 5;   // n row within tile (0..7), broadcast in warp

    float s = 0.f, kc = 0.f;   // Kahan pair

    #pragma unroll
    for (int grp = 0; grp < 16; ++grp) {
        const int d0 = grp * 8;
        const ulonglong2 pa = *reinterpret_cast<const ulonglong2*>(&ps[cl][d0]);
        const ulonglong2 pb = *reinterpret_cast<const ulonglong2*>(&ps[cl][d0 + 4]);
        const ulonglong2 fa = *reinterpret_cast<const ulonglong2*>(&fs[ng][d0]);
        const ulonglong2 fb = *reinterpret_cast<const ulonglong2*>(&fs[ng][d0 + 4]);
        unsigned long long t0 = add2(pa.x, fa.x);   // d0,d1
        unsigned long long t1 = add2(pa.y, fa.y);   // d2,d3
        unsigned long long t2 = add2(pb.x, fb.x);   // d4,d5
        unsigned long long t3 = add2(pb.y, fb.y);   // d6,d7
        unsigned long long g2 = mul2(t0, t0);
        g2 = fma2(t1, t1, g2);
        g2 = fma2(t2, t2, g2);
        g2 = fma2(t3, t3, g2);
        float g = hadd2(g2);                        // evens + odds
        float y  = __fsub_rn(g, kc);                // Kahan accumulate
        float sn = __fadd_rn(s, y);
        kc = __fsub_rn(__fsub_rn(sn, s), y);
        s  = sn;
    }

    const int c = c0 + cl;
    if (c >= CC) return;
    out[(n0 + ng) * CC + c] = epilogue(s, kc, logc[c]);
}

extern "C" void kernel_launch(void* const* d_in, const int* in_sizes, int n_in,
                              void* d_out, int out_size) {
    const float* feat  = (const float*)d_in[0];
    // d_in[1]: labels (int64) — unused by the deterministic forward math.
    const float* Ave   = (const float*)d_in[2];
    const float* kappa = (const float*)d_in[3];
    const float* logc  = (const float*)d_in[4];
    float* out = (float*)d_out;

    setup_kernel<<<CPAD / 8, 256>>>(Ave, kappa);
    proco_kernel<<<dim3((CC + TC - 1) / TC, NB / TN), 256>>>(feat, logc, out);
}

// round 12
// speedup vs baseline: 1.9867x; 1.0152x over previous
#include <cuda_runtime.h>
#include <math.h>

// ProCoUNLoss — two kernels; proco does 2 outputs/thread to halve smem
// crossbar traffic, packed-f32x2 Kahan reduce, slim f32 epilogue.
// Per-element f32 ops mirror the reference; reductions exact; x and L
// bit-exact; lnu ~1e-6 incl. the reference's Miller contamination.

namespace {
constexpr int NB   = 256;
constexpr int DD   = 128;
constexpr int CC   = 1000;
constexpr int CPAD = 1024;
constexpr int TN   = 16;   // n tile (2 outputs/thread)
constexpr int TC   = 32;   // c tile
}

__device__ float g_proto[CPAD * DD];  // fl(kappa * Ave_norm), zero padded

// ---------- packed f32x2 helpers ----------
__device__ __forceinline__ unsigned long long add2(unsigned long long a,
                                                   unsigned long long b) {
    unsigned long long r;
    asm("add.rn.f32x2 %0, %1, %2;" : "=l"(r) : "l"(a), "l"(b));
    return r;
}
__device__ __forceinline__ unsigned long long sub2(unsigned long long a,
                                                   unsigned long long b) {
    unsigned long long r;
    asm("sub.rn.f32x2 %0, %1, %2;" : "=l"(r) : "l"(a), "l"(b));
    return r;
}
__device__ __forceinline__ unsigned long long mul2(unsigned long long a,
                                                   unsigned long long b) {
    unsigned long long r;
    asm("mul.rn.f32x2 %0, %1, %2;" : "=l"(r) : "l"(a), "l"(b));
    return r;
}
__device__ __forceinline__ unsigned long long fma2(unsigned long long a,
                                                   unsigned long long b,
                                                   unsigned long long c) {
    unsigned long long r;
    asm("fma.rn.f32x2 %0, %1, %2, %3;" : "=l"(r) : "l"(a), "l"(b), "l"(c));
    return r;
}
__device__ __forceinline__ void unpack2(unsigned long long v, float& lo, float& hi) {
    unsigned int l, h;
    asm("mov.b64 {%0, %1}, %2;" : "=r"(l), "=r"(h) : "l"(v));
    lo = __uint_as_float(l); hi = __uint_as_float(h);
}

// ---------- double-single log (only for L, which needs bit-exactness) ----
__device__ __forceinline__ float2 ds_log_core(float mh, float ef) {
    float ah = __fadd_rn(mh, -1.0f);               // exact (Sterbenz)
    float bh = __fadd_rn(mh, 1.0f);
    float tb = __fsub_rn(bh, 1.0f);                // TwoSum residual for m+1
    float bl = __fadd_rn(__fsub_rn(1.0f, __fsub_rn(bh, tb)), __fsub_rn(mh, tb));
    float uh = __fdiv_rn(ah, bh);                  // u = (m-1)/(m+1), DS
    float rr = __fmaf_rn(-uh, bh, ah);
    rr = __fadd_rn(rr, -__fmul_rn(uh, bl));
    float ul = __fdiv_rn(rr, bh);
    float u2 = __fmul_rn(uh, uh);                  // atanh series to u^9
    float p  = u2 * __fmaf_rn(u2, __fmaf_rn(u2, __fmaf_rn(u2, 0.11111111f,
                    0.14285715f), 0.2f), 0.33333334f);
    float lnmh = __fmul_rn(2.0f, uh);              // exact
    float lnml = __fmaf_rn(lnmh, p, __fmul_rn(2.0f, ul));
    const float LN2H = 0.6931471824645996f;
    const float LN2L = -1.9046542e-9f;
    float eh = __fmul_rn(ef, LN2H);
    float el = __fmaf_rn(ef, LN2H, -eh);
    el = __fmaf_rn(ef, LN2L, el);
    float sh = __fadd_rn(eh, lnmh);                // TwoSum(eh, lnmh)
    float ts = __fsub_rn(sh, eh);
    float sl = __fadd_rn(__fsub_rn(eh, __fsub_rn(sh, ts)), __fsub_rn(lnmh, ts));
    return make_float2(sh, __fadd_rn(sl, __fadd_rn(el, lnml)));
}

__device__ __forceinline__ float ds_log_f32(float x) {  // fl32(log(x)), ~exact
    int ix = __float_as_int(x);
    int e  = ((ix >> 23) & 255) - 127;
    float m = __int_as_float((ix & 0x007fffff) | 0x3f800000);
    if (m > 1.4142135f) { m *= 0.5f; e += 1; }
    float2 r = ds_log_core(m, (float)e);
    return __fadd_rn(r.x, r.y);
}

// log1p(v), v in (0.02, 0.9]: 2*atanh(u), u=v/(2+v), series to u^11 (~1.5e-7)
__device__ __forceinline__ float log1p_v(float v) {
    float u  = __fdiv_rn(v, __fadd_rn(2.0f, v));
    float u2 = __fmul_rn(u, u);
    float p  = __fmaf_rn(u2, __fmaf_rn(u2, __fmaf_rn(u2, __fmaf_rn(u2,
                 0.09090909f, 0.11111111f), 0.14285715f), 0.2f), 0.33333334f);
    return __fmul_rn(__fadd_rn(u, u), __fmaf_rn(u2, p, 1.0f));
}

// log1p(z), z in [0, 0.19]: series to z^7 (abs err < 2e-7)
__device__ __forceinline__ float log1p_small(float z) {
    float r = __fmaf_rn(z, 0.14285715f, -0.16666667f);
    r = __fmaf_rn(z, r, 0.2f);
    r = __fmaf_rn(z, r, -0.25f);
    r = __fmaf_rn(z, r, 0.33333334f);
    r = __fmaf_rn(z, r, -0.5f);
    r = __fmaf_rn(z, r, 1.0f);
    return __fmul_rn(z, r);
}

// p(t) = u1(t)/63 + u2(t)/63^2 + u3(t)/63^3  (Debye u-polynomials)
__device__ __forceinline__ float pser_f(float t) {
    float t2 = t * t;
    float a = t * (3.0f - 5.0f * t2) * (1.0f / 1512.0f);
    float b = t2 * (81.0f + t2 * (-462.0f + 385.0f * t2)) * 2.1870954e-7f;
    float c = t2 * t * (30375.0f + t2 * (-369603.0f + t2 * (765765.0f - 425425.0f * t2)))
              * 9.643249e-12f;
    return a + b + c;
}

// Miller-recurrence contamination of the reference (start M=126):
// log1p(-rho63) - log1p(rho0). lp63 = log1p((63+dw63)/x) from caller.
__device__ __forceinline__ float miller_corr(float x, float w63, float lp63) {
    float w127  = __fsqrt_rn(__fmaf_rn(x, x, 16129.0f));
    float dw127 = __fdividef(16129.0f, __fadd_rn(w127, x));
    float L127  = __logf(__fadd_rn(1.0f,
                     __fdividef(__fadd_rn(127.0f, dw127), x)));
    float g63 = __fmaf_rn(-254.0f, L127, __fmaf_rn(126.0f, lp63,
                  2.0f * __fdividef(12160.0f, __fadd_rn(w127, w63))));
    float g0  = __fmaf_rn(-254.0f, L127, __fadd_rn(dw127, dw127));
    float r63 = __expf(g63);   // underflow to 0 at small x: correct
    float r0  = __expf(g0);
    return -(r63 + r0) - 0.5f * (r63 * r63 - r0 * r0);
}

// Per-element epilogue: exact-sum -> x -> lnu -> reference association.
__device__ __forceinline__ float epilogue(float s, float kc, float lc) {
    // x = f32(sqrt(s+kc)) via Newton-refined sqrt (bit-matches f64 path)
    float r0  = __fsqrt_rn(s);
    float e1  = __fmaf_rn(r0, r0, -s);
    float num = __fsub_rn(e1, kc);
    float x   = __fsub_rn(r0, __fdiv_rn(num, __fadd_rn(r0, r0)));

    float w   = __fsqrt_rn(__fmaf_rn(x, x, 3969.0f));
    float dwx = __fdiv_rn(3969.0f, __fadd_rn(w, x));   // w - x, stable
    float v   = __fdiv_rn(__fadd_rn(63.0f, dwx), x);

    float lp  = log1p_v(v);                            // log1p(v), ~1.5e-7
    float L   = ds_log_f32(x);                         // bit-exact f32 log

    float hlw = 0.5f * __fadd_rn(L, log1p_small(__fdividef(dwx, x)));
    float pp  = pser_f(__fdividef(63.0f, w));
    float lnS = __fmaf_rn(-0.5f * pp, pp, pp);         // log1p(pp)
    float corr = miller_corr(x, w, lp);

    // lnu = dwx - 63*lp - hlw - 0.5*log(2pi) + lnS + corr  (budget ~3e-6)
    float lnu = __fmaf_rn(-63.0f, lp, dwx);
    lnu = __fsub_rn(lnu, hlw);
    lnu = __fadd_rn(lnu, -0.91893853f);
    lnu = __fadd_rn(lnu, lnS);
    lnu = __fadd_rn(lnu, corr);

    // Reference's f32 association: ((lnu + x) - 63*L) - logc
    return __fsub_rn(__fsub_rn(__fadd_rn(lnu, x), __fmul_rn(63.0f, L)), lc);
}

// Exact combine of packed Kahan state (S=(se,so), K=(ke,ko)) into (hi, lo).
__device__ __forceinline__ void combine_exact(unsigned long long S,
                                              unsigned long long K,
                                              float& hi, float& lo) {
    float se, so, ke, ko;
    unpack2(S, se, so);
    unpack2(K, ke, ko);
    float h = __fadd_rn(se, so);                   // TwoSum(se, so)
    float t = __fsub_rn(h, se);
    float l = __fadd_rn(__fsub_rn(se, __fsub_rn(h, t)), __fsub_rn(so, t));
    hi = h;
    lo = __fadd_rn(l, __fadd_rn(ke, ko));
}

// Warp per class (norm computed ONCE per class): exact f64 tree norm, then
// proto = fl(kappa * div(Ave, nrm)) with Markstein correctly-rounded division.
__global__ void setup_kernel(const float* __restrict__ Ave,
                             const float* __restrict__ kappa) {
    const int w    = threadIdx.x >> 5;
    const int lane = threadIdx.x & 31;
    const int c    = blockIdx.x * 8 + w;
    if (c >= CPAD) return;

    if (c < CC) {
        float r0 = Ave[c * DD + lane];
        float r1 = Ave[c * DD + lane + 32];
        float r2 = Ave[c * DD + lane + 64];
        float r3 = Ave[c * DD + lane + 96];
        double s = (double)__fmul_rn(r0, r0);
        s += (double)__fmul_rn(r1, r1);
        s += (double)__fmul_rn(r2, r2);
        s += (double)__fmul_rn(r3, r3);
        #pragma unroll
        for (int off = 16; off; off >>= 1)
            s += __shfl_xor_sync(0xffffffffu, s, off);
        float nrm = fmaxf((float)sqrt(s), 1e-12f);
        float kap = kappa[c];
        float rh  = __frcp_rn(nrm);
        #define MDIV(a, dst) { float q0 = __fmul_rn((a), rh);                   \
            float e = __fmaf_rn(-nrm, q0, (a));                                 \
            float q = __fmaf_rn(e, rh, q0);                                     \
            dst = __fmul_rn(kap, q); }
        MDIV(r0, g_proto[c * DD + lane])
        MDIV(r1, g_proto[c * DD + lane + 32])
        MDIV(r2, g_proto[c * DD + lane + 64])
        MDIV(r3, g_proto[c * DD + lane + 96])
        #undef MDIV
    } else {
        #pragma unroll
        for (int j = 0; j < 4; ++j)
            g_proto[c * DD + lane + 32 * j] = 0.0f;
    }
}

// 16n x 32c tile, 256 threads, 2 outputs/thread (n rows ng, ng+8 share every
// ps load). Exact sum via packed-f32x2 group-of-8 + packed Kahan + exact
// final combine.
__global__ __launch_bounds__(256, 4)
void proco_kernel(const float* __restrict__ feat,
                  const float* __restrict__ logc,
                  float* __restrict__ out) {
    __shared__ float fs[TN][DD + 4];
    __shared__ float ps[TC][DD + 4];

    const int c0  = blockIdx.x * TC;
    const int n0  = blockIdx.y * TN;
    const int tid = threadIdx.x;

    for (int i = tid; i < TN * DD / 4; i += 256) {
        int r = i >> 5, q = i & 31;
        *reinterpret_cast<float4*>(&fs[r][4 * q]) =
            reinterpret_cast<const float4*>(feat)[(n0 + r) * (DD / 4) + q];
    }
    for (int i = tid; i < TC * DD / 4; i += 256) {
        int r = i >> 5, q = i & 31;
        *reinterpret_cast<float4*>(&ps[r][4 * q]) =
            reinterpret_cast<const float4*>(g_proto)[(c0 + r) * (DD / 4) + q];
    }
    __syncthreads();

    const int cl = tid & 31;   // class lane (coalesced stores)
    const int ng = tid >> 5;   // thread owns n rows ng and ng+8

    unsigned long long S0 = 0ull, K0 = 0ull;  // packed Kahan pairs
    unsigned long long S1 = 0ull, K1 = 0ull;

    #pragma unroll
    for (int grp = 0; grp < 16; ++grp) {
        const int d0 = grp * 8;
        const ulonglong2 pa = *reinterpret_cast<const ulonglong2*>(&ps[cl][d0]);
        const ulonglong2 pb = *reinterpret_cast<const ulonglong2*>(&ps[cl][d0 + 4]);
        #define GROUP(row, S, K) {                                              \
            const ulonglong2 fa = *reinterpret_cast<const ulonglong2*>(&fs[row][d0]);     \
            const ulonglong2 fb = *reinterpret_cast<const ulonglong2*>(&fs[row][d0 + 4]); \
            unsigned long long t0 = add2(pa.x, fa.x);                           \
            unsigned long long t1 = add2(pa.y, fa.y);                           \
            unsigned long long t2 = add2(pb.x, fb.x);                           \
            unsigned long long t3 = add2(pb.y, fb.y);                           \
            unsigned long long g2 = mul2(t0, t0);                               \
            g2 = fma2(t1, t1, g2);                                              \
            g2 = fma2(t2, t2, g2);                                              \
            g2 = fma2(t3, t3, g2);                                              \
            unsigned long long y  = sub2(g2, K);                                \
            unsigned long long sn = add2(S, y);                                 \
            K = sub2(sub2(sn, S), y);                                           \
            S = sn; }
        GROUP(ng,     S0, K0)
        GROUP(ng + 8, S1, K1)
        #undef GROUP
    }

    const int c = c0 + cl;
    if (c >= CC) return;
    const float lc = logc[c];

    float h0, l0, h1, l1;
    combine_exact(S0, K0, h0, l0);
    combine_exact(S1, K1, h1, l1);
    out[(n0 + ng)     * CC + c] = epilogue(h0, l0, lc);
    out[(n0 + ng + 8) * CC + c] = epilogue(h1, l1, lc);
}

extern "C" void kernel_launch(void* const* d_in, const int* in_sizes, int n_in,
                              void* d_out, int out_size) {
    const float* feat  = (const float*)d_in[0];
    // d_in[1]: labels (int64) — unused by the deterministic forward math.
    const float* Ave   = (const float*)d_in[2];
    const float* kappa = (const float*)d_in[3];
    const float* logc  = (const float*)d_in[4];
    float* out = (float*)d_out;

    setup_kernel<<<CPAD / 8, 256>>>(Ave, kappa);
    proco_kernel<<<dim3((CC + TC - 1) / TC, NB / TN), 256>>>(feat, logc, out);
}

// round 13
// speedup vs baseline: 2.3113x; 1.1634x over previous
#include <cuda_runtime.h>
#include <math.h>

// ProCoUNLoss — two kernels with PDL overlap; proco: 16c x 16n tile, 128 thr,
// 2 outputs/thread, packed-f32x2 group-16 reduce + Kahan, rcp-slim epilogue.
// Per-element f32 ops mirror the reference; reductions exact; x and L
// bit-exact; lnu ~2e-6 incl. the reference's Miller contamination.

namespace {
constexpr int NB   = 256;
constexpr int DD   = 128;
constexpr int CC   = 1000;
constexpr int CPAD = 1024;
constexpr int TN   = 16;   // n tile (2 outputs/thread)
constexpr int TC   = 16;   // c tile
}

__device__ float g_proto[CPAD * DD];  // fl(kappa * Ave_norm), zero padded

// ---------- packed f32x2 helpers ----------
__device__ __forceinline__ unsigned long long add2(unsigned long long a,
                                                   unsigned long long b) {
    unsigned long long r;
    asm("add.rn.f32x2 %0, %1, %2;" : "=l"(r) : "l"(a), "l"(b));
    return r;
}
__device__ __forceinline__ unsigned long long sub2(unsigned long long a,
                                                   unsigned long long b) {
    unsigned long long r;
    asm("sub.rn.f32x2 %0, %1, %2;" : "=l"(r) : "l"(a), "l"(b));
    return r;
}
__device__ __forceinline__ unsigned long long mul2(unsigned long long a,
                                                   unsigned long long b) {
    unsigned long long r;
    asm("mul.rn.f32x2 %0, %1, %2;" : "=l"(r) : "l"(a), "l"(b));
    return r;
}
__device__ __forceinline__ unsigned long long fma2(unsigned long long a,
                                                   unsigned long long b,
                                                   unsigned long long c) {
    unsigned long long r;
    asm("fma.rn.f32x2 %0, %1, %2, %3;" : "=l"(r) : "l"(a), "l"(b), "l"(c));
    return r;
}
__device__ __forceinline__ void unpack2(unsigned long long v, float& lo, float& hi) {
    unsigned int l, h;
    asm("mov.b64 {%0, %1}, %2;" : "=r"(l), "=r"(h) : "l"(v));
    lo = __uint_as_float(l); hi = __uint_as_float(h);
}

// rcp with one Newton step: ~1 ulp (MUFU.RCP + 2 fma)
__device__ __forceinline__ float rcp1(float b) {
    float r;
    asm("rcp.approx.ftz.f32 %0, %1;" : "=f"(r) : "f"(b));
    float e = __fmaf_rn(-b, r, 1.0f);
    return __fmaf_rn(r, e, r);
}

// ---------- double-single log (for L, which needs bit-exactness) ----------
__device__ __forceinline__ float2 ds_log_core(float mh, float ef) {
    float ah = __fadd_rn(mh, -1.0f);               // exact (Sterbenz)
    float bh = __fadd_rn(mh, 1.0f);
    float tb = __fsub_rn(bh, 1.0f);                // TwoSum residual for m+1
    float bl = __fadd_rn(__fsub_rn(1.0f, __fsub_rn(bh, tb)), __fsub_rn(mh, tb));
    float rb = rcp1(bh);
    float uh = __fmul_rn(ah, rb);                  // ~(m-1)/(m+1); residual fixes
    float rr = __fmaf_rn(-uh, bh, ah);             // exact defect
    rr = __fadd_rn(rr, -__fmul_rn(uh, bl));
    float ul = __fmul_rn(rr, rb);
    float u2 = __fmul_rn(uh, uh);                  // atanh series to u^9
    float p  = u2 * __fmaf_rn(u2, __fmaf_rn(u2, __fmaf_rn(u2, 0.11111111f,
                    0.14285715f), 0.2f), 0.33333334f);
    float lnmh = __fmul_rn(2.0f, uh);              // exact
    float lnml = __fmaf_rn(lnmh, p, __fmul_rn(2.0f, ul));
    const float LN2H = 0.6931471824645996f;
    const float LN2L = -1.9046542e-9f;
    float eh = __fmul_rn(ef, LN2H);
    float el = __fmaf_rn(ef, LN2H, -eh);
    el = __fmaf_rn(ef, LN2L, el);
    float sh = __fadd_rn(eh, lnmh);                // TwoSum(eh, lnmh)
    float ts = __fsub_rn(sh, eh);
    float sl = __fadd_rn(__fsub_rn(eh, __fsub_rn(sh, ts)), __fsub_rn(lnmh, ts));
    return make_float2(sh, __fadd_rn(sl, __fadd_rn(el, lnml)));
}

__device__ __forceinline__ float ds_log_f32(float x) {  // fl32(log(x))
    int ix = __float_as_int(x);
    int e  = ((ix >> 23) & 255) - 127;
    float m = __int_as_float((ix & 0x007fffff) | 0x3f800000);
    if (m > 1.4142135f) { m *= 0.5f; e += 1; }
    float2 r = ds_log_core(m, (float)e);
    return __fadd_rn(r.x, r.y);
}

// log1p(v), v in (0.02, 0.9]: 2*atanh(u), u=v/(2+v), series to u^11 (~2e-8)
__device__ __forceinline__ float log1p_v(float v) {
    float u  = __fmul_rn(v, rcp1(__fadd_rn(2.0f, v)));
    float u2 = __fmul_rn(u, u);
    float p  = __fmaf_rn(u2, __fmaf_rn(u2, __fmaf_rn(u2, __fmaf_rn(u2,
                 0.09090909f, 0.11111111f), 0.14285715f), 0.2f), 0.33333334f);
    return __fmul_rn(__fadd_rn(u, u), __fmaf_rn(u2, p, 1.0f));
}

// log1p(z), z in [0, 0.19]: series to z^7 (abs err < 2e-7)
__device__ __forceinline__ float log1p_small(float z) {
    float r = __fmaf_rn(z, 0.14285715f, -0.16666667f);
    r = __fmaf_rn(z, r, 0.2f);
    r = __fmaf_rn(z, r, -0.25f);
    r = __fmaf_rn(z, r, 0.33333334f);
    r = __fmaf_rn(z, r, -0.5f);
    r = __fmaf_rn(z, r, 1.0f);
    return __fmul_rn(z, r);
}

// p(t) = u1(t)/63 + u2(t)/63^2 + u3(t)/63^3  (Debye u-polynomials)
__device__ __forceinline__ float pser_f(float t) {
    float t2 = t * t;
    float a = t * (3.0f - 5.0f * t2) * (1.0f / 1512.0f);
    float b = t2 * (81.0f + t2 * (-462.0f + 385.0f * t2)) * 2.1870954e-7f;
    float c = t2 * t * (30375.0f + t2 * (-369603.0f + t2 * (765765.0f - 425425.0f * t2)))
              * 9.643249e-12f;
    return a + b + c;
}

// Miller-recurrence contamination of the reference (start M=126):
// log1p(-rho63) - log1p(rho0). lp63 = log1p((63+dw63)/x) from caller.
__device__ __forceinline__ float miller_corr(float x, float w63, float lp63) {
    float w127  = __fsqrt_rn(__fmaf_rn(x, x, 16129.0f));
    float dw127 = __fdividef(16129.0f, __fadd_rn(w127, x));
    float L127  = __logf(__fadd_rn(1.0f,
                     __fdividef(__fadd_rn(127.0f, dw127), x)));
    float g63 = __fmaf_rn(-254.0f, L127, __fmaf_rn(126.0f, lp63,
                  2.0f * __fdividef(12160.0f, __fadd_rn(w127, w63))));
    float g0  = __fmaf_rn(-254.0f, L127, __fadd_rn(dw127, dw127));
    float r63 = __expf(g63);   // underflow to 0 at small x: correct
    float r0  = __expf(g0);
    return -(r63 + r0) - 0.5f * (r63 * r63 - r0 * r0);
}

// Per-element epilogue: exact-sum -> x -> lnu -> reference association.
__device__ __forceinline__ float epilogue(float s, float kc, float lc) {
    // x = f32(sqrt(s+kc)) via Newton-refined sqrt
    float r0  = __fsqrt_rn(s);
    float e1  = __fmaf_rn(r0, r0, -s);
    float num = __fsub_rn(e1, kc);
    float x   = __fsub_rn(r0, __fmul_rn(__fmul_rn(0.5f, num), rcp1(r0)));

    float w   = __fsqrt_rn(__fmaf_rn(x, x, 3969.0f));
    float dwx = __fmul_rn(3969.0f, rcp1(__fadd_rn(w, x)));  // w - x, stable
    float rx  = rcp1(x);
    float v   = __fmul_rn(__fadd_rn(63.0f, dwx), rx);

    float lp  = log1p_v(v);                            // log1p(v)
    float L   = ds_log_f32(x);                         // bit-exact f32 log

    float hlw = 0.5f * __fadd_rn(L, log1p_small(__fmul_rn(dwx, rx)));
    float pp  = pser_f(__fdividef(63.0f, w));
    float lnS = __fmaf_rn(-0.5f * pp, pp, pp);         // log1p(pp)
    float corr = miller_corr(x, w, lp);

    // lnu = dwx - 63*lp - hlw - 0.5*log(2pi) + lnS + corr
    float lnu = __fmaf_rn(-63.0f, lp, dwx);
    lnu = __fsub_rn(lnu, hlw);
    lnu = __fadd_rn(lnu, -0.91893853f);
    lnu = __fadd_rn(lnu, lnS);
    lnu = __fadd_rn(lnu, corr);

    // Reference's f32 association: ((lnu + x) - 63*L) - logc
    return __fsub_rn(__fsub_rn(__fadd_rn(lnu, x), __fmul_rn(63.0f, L)), lc);
}

// Exact combine of packed Kahan state (S=(se,so), K=(ke,ko)) into (hi, lo).
__device__ __forceinline__ void combine_exact(unsigned long long S,
                                              unsigned long long K,
                                              float& hi, float& lo) {
    float se, so, ke, ko;
    unpack2(S, se, so);
    unpack2(K, ke, ko);
    float h = __fadd_rn(se, so);                   // TwoSum(se, so)
    float t = __fsub_rn(h, se);
    float l = __fadd_rn(__fsub_rn(se, __fsub_rn(h, t)), __fsub_rn(so, t));
    hi = h;
    lo = __fadd_rn(l, __fadd_rn(ke, ko));
}

// Warp per class: exact f64 tree norm (once per class), Markstein division.
// Signals PDL completion at the end (all threads reach it).
__global__ void setup_kernel(const float* __restrict__ Ave,
                             const float* __restrict__ kappa) {
    const int w    = threadIdx.x >> 5;
    const int lane = threadIdx.x & 31;
    const int c    = blockIdx.x * 8 + w;   // always < CPAD by construction

    if (c < CC) {
        float r0 = Ave[c * DD + lane];
        float r1 = Ave[c * DD + lane + 32];
        float r2 = Ave[c * DD + lane + 64];
        float r3 = Ave[c * DD + lane + 96];
        double s = (double)__fmul_rn(r0, r0);
        s += (double)__fmul_rn(r1, r1);
        s += (double)__fmul_rn(r2, r2);
        s += (double)__fmul_rn(r3, r3);
        #pragma unroll
        for (int off = 16; off; off >>= 1)
            s += __shfl_xor_sync(0xffffffffu, s, off);
        float nrm = fmaxf((float)sqrt(s), 1e-12f);
        float kap = kappa[c];
        float rh  = __frcp_rn(nrm);
        #define MDIV(a, dst) { float q0 = __fmul_rn((a), rh);                   \
            float e = __fmaf_rn(-nrm, q0, (a));                                 \
            float q = __fmaf_rn(e, rh, q0);                                     \
            dst = __fmul_rn(kap, q); }
        MDIV(r0, g_proto[c * DD + lane])
        MDIV(r1, g_proto[c * DD + lane + 32])
        MDIV(r2, g_proto[c * DD + lane + 64])
        MDIV(r3, g_proto[c * DD + lane + 96])
        #undef MDIV
    } else {
        #pragma unroll
        for (int j = 0; j < 4; ++j)
            g_proto[c * DD + lane + 32 * j] = 0.0f;
    }
    // PDL: this block's g_proto stores are done; let dependents proceed.
    asm volatile("griddepcontrol.launch_dependents;");
}

// 16n x 16c tile, 128 threads, 2 outputs/thread (rows ng, ng+8 share every
// ps load). Group-of-16 packed reduce, dual fma chains, Kahan across 8.
template <bool USE_PDL>
__global__ __launch_bounds__(128, 8)
void proco_kernel(const float* __restrict__ feat,
                  const float* __restrict__ logc,
                  float* __restrict__ out) {
    __shared__ __align__(16) float fs[TN][DD + 4];
    __shared__ __align__(16) float ps[TC][DD + 4];

    const int c0  = blockIdx.x * TC;
    const int n0  = blockIdx.y * TN;
    const int tid = threadIdx.x;

    // feat tile first (independent of setup) ...
    #pragma unroll
    for (int k = 0; k < 4; ++k) {
        int i = tid + 128 * k;           // 512 float4 total
        int r = i >> 5, q = i & 31;
        *reinterpret_cast<float4*>(&fs[r][4 * q]) =
            reinterpret_cast<const float4*>(feat)[(n0 + r) * (DD / 4) + q];
    }
    // ... then wait for setup's g_proto before touching it.
    if (USE_PDL) asm volatile("griddepcontrol.wait;");
    #pragma unroll
    for (int k = 0; k < 4; ++k) {
        int i = tid + 128 * k;
        int r = i >> 5, q = i & 31;
        *reinterpret_cast<float4*>(&ps[r][4 * q]) =
            reinterpret_cast<const float4*>(g_proto)[(c0 + r) * (DD / 4) + q];
    }
    __syncthreads();

    const int cl = tid & 15;   // class lane (coalesced 64B store segments)
    const int ng = tid >> 4;   // thread owns n rows ng and ng+8

    unsigned long long S0 = 0ull, K0 = 0ull;  // packed Kahan pairs
    unsigned long long S1 = 0ull, K1 = 0ull;

    #pragma unroll
    for (int grp = 0; grp < 8; ++grp) {       // 8 groups of 16 elements
        const int d0 = grp * 16;
        const ulonglong2 pa = *reinterpret_cast<const ulonglong2*>(&ps[cl][d0]);
        const ulonglong2 pb = *reinterpret_cast<const ulonglong2*>(&ps[cl][d0 + 4]);
        const ulonglong2 pc = *reinterpret_cast<const ulonglong2*>(&ps[cl][d0 + 8]);
        const ulonglong2 pd = *reinterpret_cast<const ulonglong2*>(&ps[cl][d0 + 12]);
        #define GROUP(row, S, K) {                                              \
            const ulonglong2 fa = *reinterpret_cast<const ulonglong2*>(&fs[row][d0]);      \
            const ulonglong2 fb = *reinterpret_cast<const ulonglong2*>(&fs[row][d0 + 4]);  \
            const ulonglong2 fc = *reinterpret_cast<const ulonglong2*>(&fs[row][d0 + 8]);  \
            const ulonglong2 fd = *reinterpret_cast<const ulonglong2*>(&fs[row][d0 + 12]); \
            unsigned long long t0 = add2(pa.x, fa.x);                           \
            unsigned long long t1 = add2(pa.y, fa.y);                           \
            unsigned long long t2 = add2(pb.x, fb.x);                           \
            unsigned long long t3 = add2(pb.y, fb.y);                           \
            unsigned long long t4 = add2(pc.x, fc.x);                           \
            unsigned long long t5 = add2(pc.y, fc.y);                           \
            unsigned long long t6 = add2(pd.x, fd.x);                           \
            unsigned long long t7 = add2(pd.y, fd.y);                           \
            unsigned long long ga = mul2(t0, t0);                               \
            ga = fma2(t1, t1, ga);                                              \
            ga = fma2(t2, t2, ga);                                              \
            ga = fma2(t3, t3, ga);                                              \
            unsigned long long gb = mul2(t4, t4);                               \
            gb = fma2(t5, t5, gb);                                              \
            gb = fma2(t6, t6, gb);                                              \
            gb = fma2(t7, t7, gb);                                              \
            unsigned long long g2 = add2(ga, gb);                               \
            unsigned long long y  = sub2(g2, K);                                \
            unsigned long long sn = add2(S, y);                                 \
            K = sub2(sub2(sn, S), y);                                           \
            S = sn; }
        GROUP(ng,     S0, K0)
        GROUP(ng + 8, S1, K1)
        #undef GROUP
    }

    const int c = c0 + cl;
    if (c >= CC) return;
    const float lc = logc[c];

    float h0, l0, h1, l1;
    combine_exact(S0, K0, h0, l0);
    combine_exact(S1, K1, h1, l1);
    out[(n0 + ng)     * CC + c] = epilogue(h0, l0, lc);
    out[(n0 + ng + 8) * CC + c] = epilogue(h1, l1, lc);
}

extern "C" void kernel_launch(void* const* d_in, const int* in_sizes, int n_in,
                              void* d_out, int out_size) {
    const float* feat  = (const float*)d_in[0];
    // d_in[1]: labels (int64) — unused by the deterministic forward math.
    const float* Ave   = (const float*)d_in[2];
    const float* kappa = (const float*)d_in[3];
    const float* logc  = (const float*)d_in[4];
    float* out = (float*)d_out;

    const dim3 grid((CC + TC - 1) / TC, NB / TN);   // (63, 16)

    setup_kernel<<<CPAD / 8, 256>>>(Ave, kappa);

    // PDL launch: proco may start its feat fill while setup drains.
    cudaLaunchConfig_t cfg = {};
    cfg.gridDim  = grid;
    cfg.blockDim = dim3(128, 1, 1);
    cudaLaunchAttribute at[1];
    at[0].id = cudaLaunchAttributeProgrammaticStreamSerialization;
    at[0].val.programmaticStreamSerializationAllowed = 1;
    cfg.attrs = at;
    cfg.numAttrs = 1;
    cudaError_t e = cudaLaunchKernelEx(&cfg, proco_kernel<true>, feat, logc, out);
    if (e != cudaSuccess) {
        // Fallback: plain serialized launch (twin kernel without the wait).
        proco_kernel<false><<<grid, 128>>>(feat, logc, out);
    }
}